// round 7
// baseline (speedup 1.0000x reference)
#include <cuda_runtime.h>

// AccRNNCell: B=512, T=512, F=64, U=512, P=32, L=3
// Persistent batch-parallel kernel, 128 CTAs x 4 batch rows, 1024 threads.
// 8 k-split groups x 128 col-threads; each thread owns 4 cols x 4 rows
// (16 MACs/k via 8 FFMA2). 32 warps/CTA for L2-latency hiding.

#define UU 512
#define FF 64
#define PP 32
#define NL 3
#define BT 4
#define TPB 1024
#define NG 8              // k-split groups
#define TT 512
#define BB 512

typedef unsigned long long u64;

// hsT + prevT + nsT + part[NG] + accS + wpart
#define SMEM_FLOATS (NL*UU*BT + UU*BT + UU*BT + NG*UU*BT + BT*PP + TPB)
#define SMEM_BYTES  (SMEM_FLOATS * 4)

__device__ __forceinline__ u64 pack2(float x, float y) {
    u64 v; asm("mov.b64 %0, {%1, %2};" : "=l"(v) : "f"(x), "f"(y)); return v;
}

// a[2c+h] = f32x2 over rows (2h,2h+1) for column j0+c.
template<int K>
__device__ __forceinline__ void gemm_rp(const float* __restrict__ W,   // + kbeg*UU + j0
                                        const float* __restrict__ S,   // + kbeg*BT
                                        u64* __restrict__ a)
{
#pragma unroll 4
    for (int k = 0; k < K; ++k) {
        float4 w = __ldg(reinterpret_cast<const float4*>(W + (size_t)k * UU));
        ulonglong2 h = *reinterpret_cast<const ulonglong2*>(S + k * BT);
        u64 w0 = pack2(w.x, w.x), w1 = pack2(w.y, w.y);
        u64 w2 = pack2(w.z, w.z), w3 = pack2(w.w, w.w);
        asm("fma.rn.f32x2 %0, %1, %2, %0;" : "+l"(a[0]) : "l"(w0), "l"(h.x));
        asm("fma.rn.f32x2 %0, %1, %2, %0;" : "+l"(a[1]) : "l"(w0), "l"(h.y));
        asm("fma.rn.f32x2 %0, %1, %2, %0;" : "+l"(a[2]) : "l"(w1), "l"(h.x));
        asm("fma.rn.f32x2 %0, %1, %2, %0;" : "+l"(a[3]) : "l"(w1), "l"(h.y));
        asm("fma.rn.f32x2 %0, %1, %2, %0;" : "+l"(a[4]) : "l"(w2), "l"(h.x));
        asm("fma.rn.f32x2 %0, %1, %2, %0;" : "+l"(a[5]) : "l"(w2), "l"(h.y));
        asm("fma.rn.f32x2 %0, %1, %2, %0;" : "+l"(a[6]) : "l"(w3), "l"(h.x));
        asm("fma.rn.f32x2 %0, %1, %2, %0;" : "+l"(a[7]) : "l"(w3), "l"(h.y));
    }
}

__device__ __forceinline__ void store_part(float* __restrict__ pp, const u64* __restrict__ a) {
#pragma unroll
    for (int c = 0; c < 4; ++c) {
        ulonglong2 v; v.x = a[2 * c]; v.y = a[2 * c + 1];
        *reinterpret_cast<ulonglong2*>(pp + c * BT) = v;
    }
}

__global__ void __launch_bounds__(TPB, 1) accrnn_persistent(
    const float* __restrict__ x,
    const float* __restrict__ WA,  const float* __restrict__ bA,
    const float* __restrict__ WB0, const float* __restrict__ bB0,
    const float* __restrict__ WBr, const float* __restrict__ bBr,
    const float* __restrict__ WC,  const float* __restrict__ bC,
    const float* __restrict__ Wout, const float* __restrict__ bout,
    float* __restrict__ out)
{
    extern __shared__ float smem[];
    float* hsT   = smem;                       // [NL][UU][BT]
    float* prevT = hsT + NL * UU * BT;         // [UU][BT]
    float* nsT   = prevT + UU * BT;            // [UU][BT]
    float* part  = nsT + UU * BT;              // [NG][UU][BT]
    float* accS  = part + NG * UU * BT;        // [BT*PP]
    float* wpart = accS + BT * PP;             // [TPB]

    const int tid = threadIdx.x;
    const int b0  = blockIdx.x * BT;
    const int grp = tid >> 7;          // 0..7
    const int ct  = tid & 127;
    const int j0  = ct * 4;

    for (int i = tid; i < NL * UU * BT; i += TPB) hsT[i] = 0.f;
    if (tid < BT * PP) accS[tid] = 0.f;
    __syncthreads();

    const int xr = (tid >> 6) & 3;
    const int xf = tid & 63;
    const float* xrow = x + ((size_t)(b0 + xr) * TT) * FF + xf;

    for (int t = 0; t < TT; ++t) {
        // ---- prevT = concat(x_t, acc) ----
        if (tid < BT * FF) prevT[xf * BT + xr] = xrow[(size_t)t * FF];
        if (tid < BT * PP) {
            int r = tid >> 5, p = tid & 31;
            prevT[(FF + p) * BT + r] = accS[tid];
        }
        __syncthreads();

        #pragma unroll
        for (int l = 0; l < NL; ++l) {
            // ---- stage 1: ns = hs[l]@WA[l] (grp0-3) + prev@WB (grp4-7) ----
            u64 a[8];
            if (grp == 0) {
                #pragma unroll
                for (int c = 0; c < 4; ++c) {
                    float b = bA[l * UU + j0 + c] +
                              ((l == 0) ? bB0[j0 + c] : bBr[(l - 1) * UU + j0 + c]);
                    a[2 * c] = a[2 * c + 1] = pack2(b, b);
                }
            } else {
                #pragma unroll
                for (int i = 0; i < 8; ++i) a[i] = 0ull;
            }
            if (grp < 4) {
                const float* Wa = WA + (size_t)l * UU * UU + j0;
                int kbeg = grp * (UU / 4);
                gemm_rp<UU / 4>(Wa + (size_t)kbeg * UU, hsT + l * UU * BT + kbeg * BT, a);
            } else if (l == 0) {
                int kbeg = (grp - 4) * ((FF + PP) / 4);
                gemm_rp<(FF + PP) / 4>(WB0 + j0 + (size_t)kbeg * UU, prevT + kbeg * BT, a);
            } else {
                const float* Wb = WBr + (size_t)(l - 1) * UU * UU + j0;
                int kbeg = (grp - 4) * (UU / 4);
                gemm_rp<UU / 4>(Wb + (size_t)kbeg * UU, prevT + kbeg * BT, a);
            }
            store_part(part + grp * UU * BT + j0 * BT, a);
            __syncthreads();
            if (tid < UU) {   // combine: 1 col per thread -> nsT and hsT[l]
                int col = tid;
                float4 s = *reinterpret_cast<float4*>(part + col * BT);
                #pragma unroll
                for (int g = 1; g < NG; ++g) {
                    float4 q = *reinterpret_cast<float4*>(part + g * UU * BT + col * BT);
                    s.x += q.x; s.y += q.y; s.z += q.z; s.w += q.w;
                }
                *reinterpret_cast<float4*>(nsT + col * BT) = s;
                *reinterpret_cast<float4*>(hsT + l * UU * BT + col * BT) = s;
            }
            __syncthreads();

            // ---- stage 2: prev' = ns @ WC[l] + bC[l], 8-way k-split ----
            u64 c[8];
            if (grp == 0) {
                #pragma unroll
                for (int cc = 0; cc < 4; ++cc) {
                    float b = bC[l * UU + j0 + cc];
                    c[2 * cc] = c[2 * cc + 1] = pack2(b, b);
                }
            } else {
                #pragma unroll
                for (int i = 0; i < 8; ++i) c[i] = 0ull;
            }
            {
                int kbeg = grp * (UU / NG);
                gemm_rp<UU / NG>(WC + (size_t)l * UU * UU + (size_t)kbeg * UU + j0,
                                 nsT + kbeg * BT, c);
            }
            store_part(part + grp * UU * BT + j0 * BT, c);
            __syncthreads();
            if (tid < UU) {   // combine -> prevT
                int col = tid;
                float4 s = *reinterpret_cast<float4*>(part + col * BT);
                #pragma unroll
                for (int g = 1; g < NG; ++g) {
                    float4 q = *reinterpret_cast<float4*>(part + g * UU * BT + col * BT);
                    s.x += q.x; s.y += q.y; s.z += q.z; s.w += q.w;
                }
                *reinterpret_cast<float4*>(prevT + col * BT) = s;
            }
            __syncthreads();
        }

        // ---- res = prev @ Wout + bout ; acc += res ; emit ----
        {
            int rp = tid & 127;
            int r = rp >> 5, p = rp & 31;
            float s = (grp == 0) ? bout[p] : 0.f;
            int kbeg = grp * (UU / NG);
            #pragma unroll 4
            for (int k = kbeg; k < kbeg + UU / NG; ++k)
                s = fmaf(prevT[k * BT + r], Wout[k * PP + p], s);
            wpart[tid] = s;
        }
        __syncthreads();
        if (tid < BT * PP) {
            int r = tid >> 5, p = tid & 31;
            float tot = 0.f;
            #pragma unroll
            for (int g = 0; g < NG; ++g) tot += wpart[tid + 128 * g];
            accS[tid] += tot;
            out[((size_t)(b0 + r) * TT + t) * PP + p] = tot;
        }
        __syncthreads();
    }
}

extern "C" void kernel_launch(void* const* d_in, const int* in_sizes, int n_in,
                              void* d_out, int out_size)
{
    const float* x    = (const float*)d_in[0];
    const float* WA   = (const float*)d_in[1];
    const float* bA   = (const float*)d_in[2];
    const float* WB0  = (const float*)d_in[3];
    const float* bB0  = (const float*)d_in[4];
    const float* WBr  = (const float*)d_in[5];
    const float* bBr  = (const float*)d_in[6];
    const float* WC   = (const float*)d_in[7];
    const float* bC   = (const float*)d_in[8];
    const float* Wout = (const float*)d_in[9];
    const float* bout = (const float*)d_in[10];
    float* out = (float*)d_out;

    cudaFuncSetAttribute(accrnn_persistent,
                         cudaFuncAttributeMaxDynamicSharedMemorySize, SMEM_BYTES);
    accrnn_persistent<<<BB / BT, TPB, SMEM_BYTES>>>(x, WA, bA, WB0, bB0, WBr, bBr,
                                                    WC, bC, Wout, bout, out);
}

// round 8
// speedup vs baseline: 1.1339x; 1.1339x over previous
#include <cuda_runtime.h>

// AccRNNCell: B=512, T=512, F=64, U=512, P=32, L=3
// Persistent batch-parallel kernel, 128 CTAs x 4 batch rows, 512 threads.
// 2 k-split groups x 256 col-threads; each thread owns 2 cols x 4 rows
// (8 MACs/k via 4 FFMA2). Explicit 16-deep weight-load batching (LDG.64)
// for L2-latency hiding within the 128-reg budget.

#define UU 512
#define FF 64
#define PP 32
#define NL 3
#define BT 4
#define TPB 512
#define NG 2
#define TT 512
#define BB 512

typedef unsigned long long u64;

// hsT + prevT + nsT + part[NG] + accS + wpart
#define SMEM_FLOATS (NL*UU*BT + UU*BT + UU*BT + NG*UU*BT + BT*PP + TPB)
#define SMEM_BYTES  (SMEM_FLOATS * 4)

__device__ __forceinline__ u64 pack2(float x, float y) {
    u64 v; asm("mov.b64 %0, {%1, %2};" : "=l"(v) : "f"(x), "f"(y)); return v;
}

// a[2c+h] = f32x2 over rows (2h,2h+1) for column j0+c (c in {0,1}).
// K must be a multiple of 16 (304, 208, 96, 512, 256 all qualify).
template<int K>
__device__ __forceinline__ void gemm_rp(const float* __restrict__ W,   // + kbeg*UU + j0
                                        const float* __restrict__ S,   // + kbeg*BT
                                        u64* __restrict__ a)
{
    for (int k0 = 0; k0 < K; k0 += 16) {
        float2 w[16];
        #pragma unroll
        for (int i = 0; i < 16; ++i)
            w[i] = __ldg(reinterpret_cast<const float2*>(W + (size_t)(k0 + i) * UU));
        #pragma unroll
        for (int i = 0; i < 16; ++i) {
            ulonglong2 h = *reinterpret_cast<const ulonglong2*>(S + (k0 + i) * BT);
            u64 w0 = pack2(w[i].x, w[i].x);
            u64 w1 = pack2(w[i].y, w[i].y);
            asm("fma.rn.f32x2 %0, %1, %2, %0;" : "+l"(a[0]) : "l"(w0), "l"(h.x));
            asm("fma.rn.f32x2 %0, %1, %2, %0;" : "+l"(a[1]) : "l"(w0), "l"(h.y));
            asm("fma.rn.f32x2 %0, %1, %2, %0;" : "+l"(a[2]) : "l"(w1), "l"(h.x));
            asm("fma.rn.f32x2 %0, %1, %2, %0;" : "+l"(a[3]) : "l"(w1), "l"(h.y));
        }
    }
}

__device__ __forceinline__ void store_part(float* __restrict__ pp, const u64* __restrict__ a) {
    ulonglong2 v0; v0.x = a[0]; v0.y = a[1];
    ulonglong2 v1; v1.x = a[2]; v1.y = a[3];
    *reinterpret_cast<ulonglong2*>(pp)      = v0;   // col j0,   rows 0..3
    *reinterpret_cast<ulonglong2*>(pp + BT) = v1;   // col j0+1, rows 0..3
}

__global__ void __launch_bounds__(TPB, 1) accrnn_persistent(
    const float* __restrict__ x,
    const float* __restrict__ WA,  const float* __restrict__ bA,
    const float* __restrict__ WB0, const float* __restrict__ bB0,
    const float* __restrict__ WBr, const float* __restrict__ bBr,
    const float* __restrict__ WC,  const float* __restrict__ bC,
    const float* __restrict__ Wout, const float* __restrict__ bout,
    float* __restrict__ out)
{
    extern __shared__ float smem[];
    float* hsT   = smem;                       // [NL][UU][BT]
    float* prevT = hsT + NL * UU * BT;         // [UU][BT]
    float* nsT   = prevT + UU * BT;            // [UU][BT]
    float* part  = nsT + UU * BT;              // [NG][UU][BT]
    float* accS  = part + NG * UU * BT;        // [BT*PP]
    float* wpart = accS + BT * PP;             // [TPB]

    const int tid = threadIdx.x;
    const int b0  = blockIdx.x * BT;
    const int grp = tid >> 8;          // 0 or 1
    const int ct  = tid & 255;
    const int j0  = ct * 2;

    for (int i = tid; i < NL * UU * BT; i += TPB) hsT[i] = 0.f;
    if (tid < BT * PP) accS[tid] = 0.f;
    __syncthreads();

    const int xr = (tid >> 6) & 3;
    const int xf = tid & 63;
    const float* xrow = x + ((size_t)(b0 + xr) * TT) * FF + xf;

    for (int t = 0; t < TT; ++t) {
        // ---- prevT = concat(x_t, acc) ----
        if (tid < BT * FF) prevT[xf * BT + xr] = xrow[(size_t)t * FF];
        if (tid < BT * PP) {
            int r = tid >> 5, p = tid & 31;
            prevT[(FF + p) * BT + r] = accS[tid];
        }
        __syncthreads();

        #pragma unroll
        for (int l = 0; l < NL; ++l) {
            // ---- stage 1: ns = hs[l]@WA[l] + prev@WB + biases ----
            u64 a[4];
            if (grp == 0) {
                float bv0 = bA[l * UU + j0] +
                            ((l == 0) ? bB0[j0] : bBr[(l - 1) * UU + j0]);
                float bv1 = bA[l * UU + j0 + 1] +
                            ((l == 0) ? bB0[j0 + 1] : bBr[(l - 1) * UU + j0 + 1]);
                a[0] = a[1] = pack2(bv0, bv0);   // col j0, rows 0..3
                a[2] = a[3] = pack2(bv1, bv1);   // col j0+1
                // fix: a[0],a[1] hold (bv0,bv0) pairs; a[2],a[3] (bv1,bv1)
            } else {
                a[0] = a[1] = a[2] = a[3] = 0ull;
            }
            const float* Wa = WA + (size_t)l * UU * UU + j0;
            if (l == 0) {
                // rebalanced: grp0 = WA[0:304); grp1 = WA[304:512) + WB0[0:96)
                if (grp == 0) {
                    gemm_rp<304>(Wa, hsT, a);
                } else {
                    gemm_rp<208>(Wa + (size_t)304 * UU, hsT + 304 * BT, a);
                    gemm_rp<FF + PP>(WB0 + j0, prevT, a);
                }
            } else {
                if (grp == 0) gemm_rp<UU>(Wa, hsT + l * UU * BT, a);
                else          gemm_rp<UU>(WBr + (size_t)(l - 1) * UU * UU + j0, prevT, a);
            }
            store_part(part + grp * UU * BT + j0 * BT, a);
            __syncthreads();
            {   // combine: 1 col per thread -> nsT and hsT[l]
                int col = tid;
                float4 s = *reinterpret_cast<float4*>(part + col * BT);
                float4 q = *reinterpret_cast<float4*>(part + UU * BT + col * BT);
                s.x += q.x; s.y += q.y; s.z += q.z; s.w += q.w;
                *reinterpret_cast<float4*>(nsT + col * BT) = s;
                *reinterpret_cast<float4*>(hsT + l * UU * BT + col * BT) = s;
            }
            __syncthreads();

            // ---- stage 2: prev' = ns @ WC[l] + bC[l], k-split halves ----
            u64 c[4];
            if (grp == 0) {
                float b0v = bC[l * UU + j0], b1v = bC[l * UU + j0 + 1];
                c[0] = c[1] = pack2(b0v, b0v);
                c[2] = c[3] = pack2(b1v, b1v);
            } else {
                c[0] = c[1] = c[2] = c[3] = 0ull;
            }
            {
                int kbeg = grp * (UU / 2);
                gemm_rp<UU / 2>(WC + (size_t)l * UU * UU + (size_t)kbeg * UU + j0,
                                nsT + kbeg * BT, c);
            }
            store_part(part + grp * UU * BT + j0 * BT, c);
            __syncthreads();
            {   // combine -> prevT
                int col = tid;
                float4 s = *reinterpret_cast<float4*>(part + col * BT);
                float4 q = *reinterpret_cast<float4*>(part + UU * BT + col * BT);
                s.x += q.x; s.y += q.y; s.z += q.z; s.w += q.w;
                *reinterpret_cast<float4*>(prevT + col * BT) = s;
            }
            __syncthreads();
        }

        // ---- res = prev @ Wout + bout ; acc += res ; emit ----
        {
            int rp = tid & 127;
            int r = rp >> 5, p = rp & 31;
            int g2 = (tid >> 7) & 3;            // 4-way k-split over 512 threads
            float s = (g2 == 0) ? bout[p] : 0.f;
            int kbeg = g2 * (UU / 4);
            #pragma unroll 8
            for (int k = kbeg; k < kbeg + UU / 4; ++k)
                s = fmaf(prevT[k * BT + r], Wout[k * PP + p], s);
            wpart[tid] = s;
        }
        __syncthreads();
        if (tid < BT * PP) {
            int r = tid >> 5, p = tid & 31;
            float tot = wpart[tid] + wpart[tid + 128] + wpart[tid + 256] + wpart[tid + 384];
            accS[tid] += tot;
            out[((size_t)(b0 + r) * TT + t) * PP + p] = tot;
        }
        __syncthreads();
    }
}

extern "C" void kernel_launch(void* const* d_in, const int* in_sizes, int n_in,
                              void* d_out, int out_size)
{
    const float* x    = (const float*)d_in[0];
    const float* WA   = (const float*)d_in[1];
    const float* bA   = (const float*)d_in[2];
    const float* WB0  = (const float*)d_in[3];
    const float* bB0  = (const float*)d_in[4];
    const float* WBr  = (const float*)d_in[5];
    const float* bBr  = (const float*)d_in[6];
    const float* WC   = (const float*)d_in[7];
    const float* bC   = (const float*)d_in[8];
    const float* Wout = (const float*)d_in[9];
    const float* bout = (const float*)d_in[10];
    float* out = (float*)d_out;

    cudaFuncSetAttribute(accrnn_persistent,
                         cudaFuncAttributeMaxDynamicSharedMemorySize, SMEM_BYTES);
    accrnn_persistent<<<BB / BT, TPB, SMEM_BYTES>>>(x, WA, bA, WB0, bB0, WBr, bBr,
                                                    WC, bC, Wout, bout, out);
}

// round 9
// speedup vs baseline: 1.2906x; 1.1381x over previous
#include <cuda_runtime.h>

// AccRNNCell: B=512, T=512, F=64, U=512, P=32, L=3
// Persistent batch-parallel kernel, 128 CTAs x 4 batch rows, 512 threads.
// R6 shape: 4 k-split groups x 128 col-threads; 4 cols x 4 rows per thread
// (16 MACs/k via 8 FFMA2). NEW: explicit 16-deep LDG.128 weight batching so
// ~16 loads are in flight per warp (256 FMA-cycles per batch >= L2 latency).

#define UU 512
#define FF 64
#define PP 32
#define NL 3
#define BT 4
#define TPB 512
#define NG 4              // k-split groups
#define TT 512
#define BB 512

typedef unsigned long long u64;

// hsT + prevT + nsT + part[NG] + accS + wpart
#define SMEM_FLOATS (NL*UU*BT + UU*BT + UU*BT + NG*UU*BT + BT*PP + TPB)
#define SMEM_BYTES  (SMEM_FLOATS * 4)

__device__ __forceinline__ u64 pack2(float x, float y) {
    u64 v; asm("mov.b64 %0, {%1, %2};" : "=l"(v) : "f"(x), "f"(y)); return v;
}

// a[2c+h] = f32x2 over rows (2h,2h+1) for column j0+c.
// Two-phase 16-deep batch: 16 LDG.128 front-batched, then 16x (LDS + 8 FFMA2).
template<int K>
__device__ __forceinline__ void gemm_rp(const float* __restrict__ W,   // + kbeg*UU + j0
                                        const float* __restrict__ S,   // + kbeg*BT
                                        u64* __restrict__ a)
{
    static_assert(K % 16 == 0, "K must be multiple of 16");
    for (int k0 = 0; k0 < K; k0 += 16) {
        float4 w[16];
        #pragma unroll
        for (int i = 0; i < 16; ++i)
            w[i] = __ldg(reinterpret_cast<const float4*>(W + (size_t)(k0 + i) * UU));
        #pragma unroll
        for (int i = 0; i < 16; ++i) {
            ulonglong2 h = *reinterpret_cast<const ulonglong2*>(S + (k0 + i) * BT);
            u64 w0 = pack2(w[i].x, w[i].x), w1 = pack2(w[i].y, w[i].y);
            u64 w2 = pack2(w[i].z, w[i].z), w3 = pack2(w[i].w, w[i].w);
            asm("fma.rn.f32x2 %0, %1, %2, %0;" : "+l"(a[0]) : "l"(w0), "l"(h.x));
            asm("fma.rn.f32x2 %0, %1, %2, %0;" : "+l"(a[1]) : "l"(w0), "l"(h.y));
            asm("fma.rn.f32x2 %0, %1, %2, %0;" : "+l"(a[2]) : "l"(w1), "l"(h.x));
            asm("fma.rn.f32x2 %0, %1, %2, %0;" : "+l"(a[3]) : "l"(w1), "l"(h.y));
            asm("fma.rn.f32x2 %0, %1, %2, %0;" : "+l"(a[4]) : "l"(w2), "l"(h.x));
            asm("fma.rn.f32x2 %0, %1, %2, %0;" : "+l"(a[5]) : "l"(w2), "l"(h.y));
            asm("fma.rn.f32x2 %0, %1, %2, %0;" : "+l"(a[6]) : "l"(w3), "l"(h.x));
            asm("fma.rn.f32x2 %0, %1, %2, %0;" : "+l"(a[7]) : "l"(w3), "l"(h.y));
        }
    }
}

__device__ __forceinline__ void store_part(float* __restrict__ pp, const u64* __restrict__ a) {
#pragma unroll
    for (int c = 0; c < 4; ++c) {
        ulonglong2 v; v.x = a[2 * c]; v.y = a[2 * c + 1];
        *reinterpret_cast<ulonglong2*>(pp + c * BT) = v;
    }
}

__global__ void __launch_bounds__(TPB, 1) accrnn_persistent(
    const float* __restrict__ x,
    const float* __restrict__ WA,  const float* __restrict__ bA,
    const float* __restrict__ WB0, const float* __restrict__ bB0,
    const float* __restrict__ WBr, const float* __restrict__ bBr,
    const float* __restrict__ WC,  const float* __restrict__ bC,
    const float* __restrict__ Wout, const float* __restrict__ bout,
    float* __restrict__ out)
{
    extern __shared__ float smem[];
    float* hsT   = smem;                       // [NL][UU][BT]
    float* prevT = hsT + NL * UU * BT;         // [UU][BT]
    float* nsT   = prevT + UU * BT;            // [UU][BT]
    float* part  = nsT + UU * BT;              // [NG][UU][BT]
    float* accS  = part + NG * UU * BT;        // [BT*PP]
    float* wpart = accS + BT * PP;             // [TPB]

    const int tid = threadIdx.x;
    const int b0  = blockIdx.x * BT;
    const int grp = tid >> 7;          // 0..3
    const int ct  = tid & 127;
    const int j0  = ct * 4;

    for (int i = tid; i < NL * UU * BT; i += TPB) hsT[i] = 0.f;
    if (tid < BT * PP) accS[tid] = 0.f;
    __syncthreads();

    const int xr = (tid >> 6) & 3;
    const int xf = tid & 63;
    const float* xrow = x + ((size_t)(b0 + xr) * TT) * FF + xf;

    for (int t = 0; t < TT; ++t) {
        // ---- prevT = concat(x_t, acc) ----
        if (tid < BT * FF) prevT[xf * BT + xr] = xrow[(size_t)t * FF];
        if (tid < BT * PP) {
            int r = tid >> 5, p = tid & 31;
            prevT[(FF + p) * BT + r] = accS[tid];
        }
        __syncthreads();

        #pragma unroll
        for (int l = 0; l < NL; ++l) {
            // ---- stage 1: ns = hs[l]@WA[l] (grp0/1) + prev@WB (grp2/3) ----
            u64 a[8];
            if (grp == 0) {
                #pragma unroll
                for (int c = 0; c < 4; ++c) {
                    float b = bA[l * UU + j0 + c] +
                              ((l == 0) ? bB0[j0 + c] : bBr[(l - 1) * UU + j0 + c]);
                    a[2 * c] = a[2 * c + 1] = pack2(b, b);
                }
            } else {
                #pragma unroll
                for (int i = 0; i < 8; ++i) a[i] = 0ull;
            }
            if (grp < 2) {
                const float* Wa = WA + (size_t)l * UU * UU + j0;
                int kbeg = grp * (UU / 2);
                gemm_rp<UU / 2>(Wa + (size_t)kbeg * UU, hsT + l * UU * BT + kbeg * BT, a);
            } else if (l == 0) {
                int kbeg = (grp - 2) * ((FF + PP) / 2);
                gemm_rp<(FF + PP) / 2>(WB0 + j0 + (size_t)kbeg * UU, prevT + kbeg * BT, a);
            } else {
                const float* Wb = WBr + (size_t)(l - 1) * UU * UU + j0;
                int kbeg = (grp - 2) * (UU / 2);
                gemm_rp<UU / 2>(Wb + (size_t)kbeg * UU, prevT + kbeg * BT, a);
            }
            store_part(part + grp * UU * BT + j0 * BT, a);
            __syncthreads();
            {   // combine: 1 col per thread -> nsT and hsT[l]
                int col = tid;
                float4 s = *reinterpret_cast<float4*>(part + col * BT);
                #pragma unroll
                for (int g = 1; g < NG; ++g) {
                    float4 q = *reinterpret_cast<float4*>(part + g * UU * BT + col * BT);
                    s.x += q.x; s.y += q.y; s.z += q.z; s.w += q.w;
                }
                *reinterpret_cast<float4*>(nsT + col * BT) = s;
                *reinterpret_cast<float4*>(hsT + l * UU * BT + col * BT) = s;
            }
            __syncthreads();

            // ---- stage 2: prev' = ns @ WC[l] + bC[l], 4-way k-split ----
            u64 c[8];
            if (grp == 0) {
                #pragma unroll
                for (int cc = 0; cc < 4; ++cc) {
                    float b = bC[l * UU + j0 + cc];
                    c[2 * cc] = c[2 * cc + 1] = pack2(b, b);
                }
            } else {
                #pragma unroll
                for (int i = 0; i < 8; ++i) c[i] = 0ull;
            }
            {
                int kbeg = grp * (UU / NG);
                gemm_rp<UU / NG>(WC + (size_t)l * UU * UU + (size_t)kbeg * UU + j0,
                                 nsT + kbeg * BT, c);
            }
            store_part(part + grp * UU * BT + j0 * BT, c);
            __syncthreads();
            {   // combine -> prevT
                int col = tid;
                float4 s = *reinterpret_cast<float4*>(part + col * BT);
                #pragma unroll
                for (int g = 1; g < NG; ++g) {
                    float4 q = *reinterpret_cast<float4*>(part + g * UU * BT + col * BT);
                    s.x += q.x; s.y += q.y; s.z += q.z; s.w += q.w;
                }
                *reinterpret_cast<float4*>(prevT + col * BT) = s;
            }
            __syncthreads();
        }

        // ---- res = prev @ Wout + bout ; acc += res ; emit ----
        {
            int rp = tid & 127;
            int r = rp >> 5, p = rp & 31;
            float s = (grp == 0) ? bout[p] : 0.f;
            int kbeg = grp * (UU / NG);
            #pragma unroll 8
            for (int k = kbeg; k < kbeg + UU / NG; ++k)
                s = fmaf(prevT[k * BT + r], Wout[k * PP + p], s);
            wpart[tid] = s;
        }
        __syncthreads();
        if (tid < BT * PP) {
            int r = tid >> 5, p = tid & 31;
            float tot = wpart[tid] + wpart[tid + 128] + wpart[tid + 256] + wpart[tid + 384];
            accS[tid] += tot;
            out[((size_t)(b0 + r) * TT + t) * PP + p] = tot;
        }
        __syncthreads();
    }
}

extern "C" void kernel_launch(void* const* d_in, const int* in_sizes, int n_in,
                              void* d_out, int out_size)
{
    const float* x    = (const float*)d_in[0];
    const float* WA   = (const float*)d_in[1];
    const float* bA   = (const float*)d_in[2];
    const float* WB0  = (const float*)d_in[3];
    const float* bB0  = (const float*)d_in[4];
    const float* WBr  = (const float*)d_in[5];
    const float* bBr  = (const float*)d_in[6];
    const float* WC   = (const float*)d_in[7];
    const float* bC   = (const float*)d_in[8];
    const float* Wout = (const float*)d_in[9];
    const float* bout = (const float*)d_in[10];
    float* out = (float*)d_out;

    cudaFuncSetAttribute(accrnn_persistent,
                         cudaFuncAttributeMaxDynamicSharedMemorySize, SMEM_BYTES);
    accrnn_persistent<<<BB / BT, TPB, SMEM_BYTES>>>(x, WA, bA, WB0, bB0, WBr, bBr,
                                                    WC, bC, Wout, bout, out);
}

// round 10
// speedup vs baseline: 1.3574x; 1.0518x over previous
#include <cuda_runtime.h>

// AccRNNCell: B=512, T=512, F=64, U=512, P=32, L=3
// Persistent batch-parallel kernel, 128 CTAs x 4 batch rows, 512 threads.
// R6 shape: 4 k-split groups x 128 col-threads; 4 cols x 4 rows per thread
// (16 MACs/k via 8 FFMA2). Weight loads software-pipelined as two 8-deep
// LDG.128 buffers so each load half is covered by the other half's FMA phase.

#define UU 512
#define FF 64
#define PP 32
#define NL 3
#define BT 4
#define TPB 512
#define NG 4              // k-split groups
#define TT 512
#define BB 512

typedef unsigned long long u64;

// hsT + prevT + nsT + part[NG] + accS + wpart
#define SMEM_FLOATS (NL*UU*BT + UU*BT + UU*BT + NG*UU*BT + BT*PP + TPB)
#define SMEM_BYTES  (SMEM_FLOATS * 4)

__device__ __forceinline__ u64 pack2(float x, float y) {
    u64 v; asm("mov.b64 %0, {%1, %2};" : "=l"(v) : "f"(x), "f"(y)); return v;
}

__device__ __forceinline__ void fma8(const float4* __restrict__ w,
                                     const float* __restrict__ S,  // + k0*BT
                                     u64* __restrict__ a)
{
    #pragma unroll
    for (int i = 0; i < 8; ++i) {
        ulonglong2 h = *reinterpret_cast<const ulonglong2*>(S + i * BT);
        u64 w0 = pack2(w[i].x, w[i].x), w1 = pack2(w[i].y, w[i].y);
        u64 w2 = pack2(w[i].z, w[i].z), w3 = pack2(w[i].w, w[i].w);
        asm("fma.rn.f32x2 %0, %1, %2, %0;" : "+l"(a[0]) : "l"(w0), "l"(h.x));
        asm("fma.rn.f32x2 %0, %1, %2, %0;" : "+l"(a[1]) : "l"(w0), "l"(h.y));
        asm("fma.rn.f32x2 %0, %1, %2, %0;" : "+l"(a[2]) : "l"(w1), "l"(h.x));
        asm("fma.rn.f32x2 %0, %1, %2, %0;" : "+l"(a[3]) : "l"(w1), "l"(h.y));
        asm("fma.rn.f32x2 %0, %1, %2, %0;" : "+l"(a[4]) : "l"(w2), "l"(h.x));
        asm("fma.rn.f32x2 %0, %1, %2, %0;" : "+l"(a[5]) : "l"(w2), "l"(h.y));
        asm("fma.rn.f32x2 %0, %1, %2, %0;" : "+l"(a[6]) : "l"(w3), "l"(h.x));
        asm("fma.rn.f32x2 %0, %1, %2, %0;" : "+l"(a[7]) : "l"(w3), "l"(h.y));
    }
}

__device__ __forceinline__ void load8(float4* __restrict__ w,
                                      const float* __restrict__ W)  // + k*UU (+j0)
{
    #pragma unroll
    for (int i = 0; i < 8; ++i)
        w[i] = __ldg(reinterpret_cast<const float4*>(W + (size_t)i * UU));
}

// a[2c+h] = f32x2 over rows (2h,2h+1) for column j0+c.
// Software-pipelined: wa/wb 8-deep buffers; each half's loads are in flight
// while the other half's FMAs issue. Last 16-k block peeled (no overrun).
template<int K>
__device__ __forceinline__ void gemm_rp(const float* __restrict__ W,   // + kbeg*UU + j0
                                        const float* __restrict__ S,   // + kbeg*BT
                                        u64* __restrict__ a)
{
    static_assert(K % 16 == 0, "K must be multiple of 16");
    float4 wa[8], wb[8];
    load8(wa, W);
    #pragma unroll 2
    for (int k0 = 0; k0 < K - 16; k0 += 16) {
        load8(wb, W + (size_t)(k0 + 8) * UU);
        fma8(wa, S + k0 * BT, a);
        load8(wa, W + (size_t)(k0 + 16) * UU);
        fma8(wb, S + (k0 + 8) * BT, a);
    }
    load8(wb, W + (size_t)(K - 8) * UU);
    fma8(wa, S + (K - 16) * BT, a);
    fma8(wb, S + (K - 8) * BT, a);
}

__device__ __forceinline__ void store_part(float* __restrict__ pp, const u64* __restrict__ a) {
#pragma unroll
    for (int c = 0; c < 4; ++c) {
        ulonglong2 v; v.x = a[2 * c]; v.y = a[2 * c + 1];
        *reinterpret_cast<ulonglong2*>(pp + c * BT) = v;
    }
}

__global__ void __launch_bounds__(TPB, 1) accrnn_persistent(
    const float* __restrict__ x,
    const float* __restrict__ WA,  const float* __restrict__ bA,
    const float* __restrict__ WB0, const float* __restrict__ bB0,
    const float* __restrict__ WBr, const float* __restrict__ bBr,
    const float* __restrict__ WC,  const float* __restrict__ bC,
    const float* __restrict__ Wout, const float* __restrict__ bout,
    float* __restrict__ out)
{
    extern __shared__ float smem[];
    float* hsT   = smem;                       // [NL][UU][BT]
    float* prevT = hsT + NL * UU * BT;         // [UU][BT]
    float* nsT   = prevT + UU * BT;            // [UU][BT]
    float* part  = nsT + UU * BT;              // [NG][UU][BT]
    float* accS  = part + NG * UU * BT;        // [BT*PP]
    float* wpart = accS + BT * PP;             // [TPB]

    const int tid = threadIdx.x;
    const int b0  = blockIdx.x * BT;
    const int grp = tid >> 7;          // 0..3
    const int ct  = tid & 127;
    const int j0  = ct * 4;

    for (int i = tid; i < NL * UU * BT; i += TPB) hsT[i] = 0.f;
    if (tid < BT * PP) accS[tid] = 0.f;
    __syncthreads();

    const int xr = (tid >> 6) & 3;
    const int xf = tid & 63;
    const float* xrow = x + ((size_t)(b0 + xr) * TT) * FF + xf;

    for (int t = 0; t < TT; ++t) {
        // ---- prevT = concat(x_t, acc) ----
        if (tid < BT * FF) prevT[xf * BT + xr] = xrow[(size_t)t * FF];
        if (tid < BT * PP) {
            int r = tid >> 5, p = tid & 31;
            prevT[(FF + p) * BT + r] = accS[tid];
        }
        __syncthreads();

        #pragma unroll
        for (int l = 0; l < NL; ++l) {
            // ---- stage 1: ns = hs[l]@WA[l] (grp0/1) + prev@WB (grp2/3) ----
            u64 a[8];
            if (grp == 0) {
                #pragma unroll
                for (int c = 0; c < 4; ++c) {
                    float b = bA[l * UU + j0 + c] +
                              ((l == 0) ? bB0[j0 + c] : bBr[(l - 1) * UU + j0 + c]);
                    a[2 * c] = a[2 * c + 1] = pack2(b, b);
                }
            } else {
                #pragma unroll
                for (int i = 0; i < 8; ++i) a[i] = 0ull;
            }
            if (grp < 2) {
                const float* Wa = WA + (size_t)l * UU * UU + j0;
                int kbeg = grp * (UU / 2);
                gemm_rp<UU / 2>(Wa + (size_t)kbeg * UU, hsT + l * UU * BT + kbeg * BT, a);
            } else if (l == 0) {
                int kbeg = (grp - 2) * ((FF + PP) / 2);
                gemm_rp<(FF + PP) / 2>(WB0 + j0 + (size_t)kbeg * UU, prevT + kbeg * BT, a);
            } else {
                const float* Wb = WBr + (size_t)(l - 1) * UU * UU + j0;
                int kbeg = (grp - 2) * (UU / 2);
                gemm_rp<UU / 2>(Wb + (size_t)kbeg * UU, prevT + kbeg * BT, a);
            }
            store_part(part + grp * UU * BT + j0 * BT, a);
            __syncthreads();
            {   // combine: 1 col per thread -> nsT and hsT[l]
                int col = tid;
                float4 s = *reinterpret_cast<float4*>(part + col * BT);
                #pragma unroll
                for (int g = 1; g < NG; ++g) {
                    float4 q = *reinterpret_cast<float4*>(part + g * UU * BT + col * BT);
                    s.x += q.x; s.y += q.y; s.z += q.z; s.w += q.w;
                }
                *reinterpret_cast<float4*>(nsT + col * BT) = s;
                *reinterpret_cast<float4*>(hsT + l * UU * BT + col * BT) = s;
            }
            __syncthreads();

            // ---- stage 2: prev' = ns @ WC[l] + bC[l], 4-way k-split ----
            u64 c[8];
            if (grp == 0) {
                #pragma unroll
                for (int cc = 0; cc < 4; ++cc) {
                    float b = bC[l * UU + j0 + cc];
                    c[2 * cc] = c[2 * cc + 1] = pack2(b, b);
                }
            } else {
                #pragma unroll
                for (int i = 0; i < 8; ++i) c[i] = 0ull;
            }
            {
                int kbeg = grp * (UU / NG);
                gemm_rp<UU / NG>(WC + (size_t)l * UU * UU + (size_t)kbeg * UU + j0,
                                 nsT + kbeg * BT, c);
            }
            store_part(part + grp * UU * BT + j0 * BT, c);
            __syncthreads();
            {   // combine -> prevT
                int col = tid;
                float4 s = *reinterpret_cast<float4*>(part + col * BT);
                #pragma unroll
                for (int g = 1; g < NG; ++g) {
                    float4 q = *reinterpret_cast<float4*>(part + g * UU * BT + col * BT);
                    s.x += q.x; s.y += q.y; s.z += q.z; s.w += q.w;
                }
                *reinterpret_cast<float4*>(prevT + col * BT) = s;
            }
            __syncthreads();
        }

        // ---- res = prev @ Wout + bout ; acc += res ; emit ----
        {
            int rp = tid & 127;
            int r = rp >> 5, p = rp & 31;
            float s = (grp == 0) ? bout[p] : 0.f;
            int kbeg = grp * (UU / NG);
            #pragma unroll 8
            for (int k = kbeg; k < kbeg + UU / NG; ++k)
                s = fmaf(prevT[k * BT + r], Wout[k * PP + p], s);
            wpart[tid] = s;
        }
        __syncthreads();
        if (tid < BT * PP) {
            int r = tid >> 5, p = tid & 31;
            float tot = wpart[tid] + wpart[tid + 128] + wpart[tid + 256] + wpart[tid + 384];
            accS[tid] += tot;
            out[((size_t)(b0 + r) * TT + t) * PP + p] = tot;
        }
        __syncthreads();
    }
}

extern "C" void kernel_launch(void* const* d_in, const int* in_sizes, int n_in,
                              void* d_out, int out_size)
{
    const float* x    = (const float*)d_in[0];
    const float* WA   = (const float*)d_in[1];
    const float* bA   = (const float*)d_in[2];
    const float* WB0  = (const float*)d_in[3];
    const float* bB0  = (const float*)d_in[4];
    const float* WBr  = (const float*)d_in[5];
    const float* bBr  = (const float*)d_in[6];
    const float* WC   = (const float*)d_in[7];
    const float* bC   = (const float*)d_in[8];
    const float* Wout = (const float*)d_in[9];
    const float* bout = (const float*)d_in[10];
    float* out = (float*)d_out;

    cudaFuncSetAttribute(accrnn_persistent,
                         cudaFuncAttributeMaxDynamicSharedMemorySize, SMEM_BYTES);
    accrnn_persistent<<<BB / BT, TPB, SMEM_BYTES>>>(x, WA, bA, WB0, bB0, WBr, bBr,
                                                    WC, bC, Wout, bout, out);
}